// round 13
// baseline (speedup 1.0000x reference)
#include <cuda_runtime.h>
#include <math.h>
#include <stdint.h>

#define CCH 1536
#define PP 512
#define HH 32
#define FF 128
#define HF 4096
#define NROWS 1024
#define NPOS 1023
#define GK 1536
#define GN 4096

// ------------------- scratch (device globals, no allocation) --------------
__device__ float g_xn[NROWS * CCH];
__device__ float g_xa[NROWS * CCH];
__device__ float g_q [NROWS * HF];
__device__ float g_k [NROWS * HF];
__device__ float g_yqk[NROWS * 256];          // [row][0:128)=yq, [128:256)=yk
__device__ float g_SB[17 * HF];
__device__ float g_T [17 * HF];
__device__ float g_Gq[NROWS * 544];
__device__ float g_Hq[NROWS * 544];
__device__ float g_Gk[NROWS * 544];
__device__ float g_Hk[NROWS * 544];
__device__ float g_QP[NROWS * 17 * FF];       // (Gq+Hq)@Wout
__device__ float g_QM[NROWS * 17 * FF];       // (Gq-Hq)@Wout
__device__ float g_KP[NROWS * 17 * FF];
__device__ float g_KM[NROWS * 17 * FF];
__device__ float g_S[(size_t)64 * PP * PP];   // [b*32+h][q][k]
__device__ float g_WqT[(size_t)GN * GK];      // K-major weights
__device__ float g_WkT[(size_t)GN * GK];
__device__ float g_WyT[(size_t)256 * GK];     // rows 0-127: WyqT, 128-255: WykT
__device__ int   g_jmin[NPOS];
__device__ float g_sign[NPOS];

// ------------------- cp.async / mma helpers -------------------------------
__device__ __forceinline__ void cp_async16(void* smem_dst, const void* gmem_src) {
    uint32_t d;
    asm("{ .reg .u64 t; cvta.to.shared.u64 t, %1; cvt.u32.u64 %0, t; }" : "=r"(d) : "l"(smem_dst));
    asm volatile("cp.async.ca.shared.global [%0], [%1], 16;" :: "r"(d), "l"(gmem_src));
}
#define CP_COMMIT() asm volatile("cp.async.commit_group;" ::: "memory")
#define CP_WAIT(n)  asm volatile("cp.async.wait_group %0;" :: "n"(n) : "memory")

__device__ __forceinline__ void mma_tf32(float* c, const float* a, const float* b) {
    asm volatile(
        "mma.sync.aligned.m16n8k8.row.col.f32.tf32.tf32.f32 "
        "{%0,%1,%2,%3}, {%4,%5,%6,%7}, {%8,%9}, {%0,%1,%2,%3};"
        : "+f"(c[0]), "+f"(c[1]), "+f"(c[2]), "+f"(c[3])
        : "r"(__float_as_uint(a[0])), "r"(__float_as_uint(a[1])),
          "r"(__float_as_uint(a[2])), "r"(__float_as_uint(a[3])),
          "r"(__float_as_uint(b[0])), "r"(__float_as_uint(b[1])));
}

__device__ __forceinline__ float tf32_rna(float x) {
    uint32_t u;
    asm("cvt.rna.tf32.f32 %0, %1;" : "=r"(u) : "f"(x));
    return __uint_as_float(u);
}

// 3xTF32 compensated mma: near-fp32 accuracy
__device__ __forceinline__ void mma_tf32x3(float* c, const float* a, const float* b) {
    float ah[4], al[4], bh[2], bl[2];
    #pragma unroll
    for (int i = 0; i < 4; i++) { ah[i] = tf32_rna(a[i]); al[i] = a[i] - ah[i]; }
    #pragma unroll
    for (int i = 0; i < 2; i++) { bh[i] = tf32_rna(b[i]); bl[i] = b[i] - bh[i]; }
    mma_tf32(c, al, bh);
    mma_tf32(c, ah, bl);
    mma_tf32(c, ah, bh);
}

// ------------------- tensor-core GEMM (tf32 mma.sync, cp.async x4) --------
// mode 0: z=0: g_q = g_xn @ WqT^T ; z=1: g_k = g_xn @ WkT^T  (K=1536) grid (32,8,2)
// mode 2: g_S = Q @ K^T per (b,h) (K=128) grid (4,4,64)
// mode 3: g_yqk = g_xa @ WyT^T   (K=1536)  grid (2,8)  [3xTF32 precise]
#define BK 16
#define SKP 20
#define NSTG 4
#define MM_SMEM (NSTG * 2 * 128 * SKP * 4)    // 81920 bytes

__global__ __launch_bounds__(256, 2) void k_mm_mma(int mode) {
    extern __shared__ float sm[];
    float (*As)[128][SKP] = (float(*)[128][SKP])sm;
    float (*Bs)[128][SKP] = (float(*)[128][SKP])(sm + NSTG * 128 * SKP);
    int tid = threadIdx.x, lane = tid & 31, wid = tid >> 5;
    int n0 = blockIdx.x * 128, m0 = blockIdx.y * 128;

    const float *A, *B; float* C;
    int lda, ldb, ldc, Kd;
    if (mode == 2) {
        int z = blockIdx.z, b = z >> 5, h = z & 31;
        A = g_q + ((size_t)(b * PP + m0)) * HF + h * FF;
        B = g_k + ((size_t)(b * PP + n0)) * HF + h * FF;
        C = g_S + ((size_t)z * PP + m0) * PP + n0;
        lda = HF; ldb = HF; ldc = PP; Kd = FF;
    } else if (mode == 3) {
        A = g_xa + (size_t)m0 * GK;
        B = g_WyT + (size_t)n0 * GK;
        C = g_yqk + (size_t)m0 * 256 + n0;
        lda = GK; ldb = GK; ldc = 256; Kd = GK;
    } else {
        int which = blockIdx.z;
        A = g_xn + (size_t)m0 * GK;
        B = (which ? g_WkT : g_WqT) + (size_t)n0 * GK;
        C = (which ? g_k : g_q) + (size_t)m0 * GN + n0;
        lda = GK; ldb = GK; ldc = GN; Kd = GK;
    }

    int lr = tid >> 2, lc = (tid & 3) * 4;
    int NS = Kd / BK;

    // preload stages 0..2
    #pragma unroll
    for (int p = 0; p < NSTG - 1; p++) {
        int k0 = p * BK;
        #pragma unroll
        for (int u = 0; u < 2; u++) {
            int r = lr + u * 64;
            cp_async16(&As[p][r][lc], A + (size_t)r * lda + k0 + lc);
            cp_async16(&Bs[p][r][lc], B + (size_t)r * ldb + k0 + lc);
        }
        CP_COMMIT();
    }

    int wm = (wid & 1) * 64;
    int wn = (wid >> 1) * 32;
    float acc[4][4][4];
    #pragma unroll
    for (int i = 0; i < 4; i++)
        #pragma unroll
        for (int j = 0; j < 4; j++)
            #pragma unroll
            for (int r = 0; r < 4; r++) acc[i][j][r] = 0.f;

    int g4 = lane >> 2, r4 = lane & 3;
    for (int kt = 0; kt < NS; kt++) {
        CP_WAIT(NSTG - 2);
        __syncthreads();
        // prefetch stage kt+3 (overwrites buffer (kt-1)&3, fully consumed)
        if (kt + NSTG - 1 < NS) {
            int p = (kt + NSTG - 1) & (NSTG - 1);
            int k0 = (kt + NSTG - 1) * BK;
            #pragma unroll
            for (int u = 0; u < 2; u++) {
                int r = lr + u * 64;
                cp_async16(&As[p][r][lc], A + (size_t)r * lda + k0 + lc);
                cp_async16(&Bs[p][r][lc], B + (size_t)r * ldb + k0 + lc);
            }
        }
        CP_COMMIT();   // commit even if empty: keeps group accounting uniform
        int s = kt & (NSTG - 1);
        #pragma unroll
        for (int kk = 0; kk < 16; kk += 8) {
            float a[4][4], b[4][2];
            #pragma unroll
            for (int mt = 0; mt < 4; mt++) {
                int m = wm + mt * 16 + g4;
                a[mt][0] = As[s][m    ][kk + r4];
                a[mt][1] = As[s][m + 8][kk + r4];
                a[mt][2] = As[s][m    ][kk + r4 + 4];
                a[mt][3] = As[s][m + 8][kk + r4 + 4];
            }
            #pragma unroll
            for (int nt = 0; nt < 4; nt++) {
                int n = wn + nt * 8 + g4;
                b[nt][0] = Bs[s][n][kk + r4];
                b[nt][1] = Bs[s][n][kk + r4 + 4];
            }
            if (mode == 3) {
                #pragma unroll
                for (int mt = 0; mt < 4; mt++)
                    #pragma unroll
                    for (int nt = 0; nt < 4; nt++)
                        mma_tf32x3(acc[mt][nt], a[mt], b[nt]);
            } else {
                #pragma unroll
                for (int mt = 0; mt < 4; mt++)
                    #pragma unroll
                    for (int nt = 0; nt < 4; nt++)
                        mma_tf32(acc[mt][nt], a[mt], b[nt]);
            }
        }
    }

    #pragma unroll
    for (int mt = 0; mt < 4; mt++) {
        #pragma unroll
        for (int nt = 0; nt < 4; nt++) {
            int m = wm + mt * 16 + g4;
            int n = wn + nt * 8 + r4 * 2;
            *(float2*)&C[(size_t)m * ldc + n] =
                make_float2(acc[mt][nt][0], acc[mt][nt][1]);
            *(float2*)&C[(size_t)(m + 8) * ldc + n] =
                make_float2(acc[mt][nt][2], acc[mt][nt][3]);
        }
    }
}

// ------------------- transposes to K-major --------------------------------
__global__ void k_tr(const float* __restrict__ W, int which) {
    __shared__ float t[32][33];
    int Cc = (which < 2) ? GN : FF;
    float* dst; int roff = 0;
    if (which == 0) dst = g_WqT;
    else if (which == 1) dst = g_WkT;
    else { dst = g_WyT; roff = (which - 2) * FF; }
    int n0 = blockIdx.x * 32, k0 = blockIdx.y * 32;
    int tx = threadIdx.x, ty = threadIdx.y;      // (32, 8)
    #pragma unroll
    for (int i = 0; i < 32; i += 8)
        t[ty + i][tx] = W[(size_t)(k0 + ty + i) * Cc + n0 + tx];
    __syncthreads();
    #pragma unroll
    for (int i = 0; i < 32; i += 8)
        dst[(size_t)(roff + n0 + ty + i) * GK + k0 + tx] = t[tx][ty + i];
}

// ------------------- avgpool + RMS scale + gelu (float4) ------------------
__global__ void k_pool(const float* __restrict__ x, const float* __restrict__ ns,
                       const float* __restrict__ nms) {
    int bp = blockIdx.x;
    size_t base = (size_t)bp * 16 * CCH;
    int c4 = threadIdx.x * 4;                 // 384 threads cover 1536
    float4 s = make_float4(0.f, 0.f, 0.f, 0.f);
    #pragma unroll
    for (int w = 0; w < 16; w++) {
        float4 v = *(const float4*)&x[base + (size_t)w * CCH + c4];
        s.x += v.x; s.y += v.y; s.z += v.z; s.w += v.w;
    }
    float4 nsv = *(const float4*)&ns[c4];
    float4 nmv = *(const float4*)&nms[c4];
    float4 vn, va;
    vn.x = s.x * 0.0625f * (nsv.x * rsqrtf(nmv.x + 1e-5f));
    vn.y = s.y * 0.0625f * (nsv.y * rsqrtf(nmv.y + 1e-5f));
    vn.z = s.z * 0.0625f * (nsv.z * rsqrtf(nmv.z + 1e-5f));
    vn.w = s.w * 0.0625f * (nsv.w * rsqrtf(nmv.w + 1e-5f));
    va.x = 0.5f * vn.x * (1.f + erff(vn.x * 0.70710678118654752f));
    va.y = 0.5f * vn.y * (1.f + erff(vn.y * 0.70710678118654752f));
    va.z = 0.5f * vn.z * (1.f + erff(vn.z * 0.70710678118654752f));
    va.w = 0.5f * vn.w * (1.f + erff(vn.w * 0.70710678118654752f));
    *(float4*)&g_xn[(size_t)bp * CCH + c4] = vn;
    *(float4*)&g_xa[(size_t)bp * CCH + c4] = va;
}

// ------------------- suffix sums of Wp (+ bp) -----------------------------
__global__ void k_suffix(const float* __restrict__ Wp, const float* __restrict__ bp) {
    int col = blockIdx.x * 256 + threadIdx.x;
    if (col >= HF) return;
    float bpv = bp[col];
    g_SB[16 * HF + col] = bpv;
    g_T [16 * HF + col] = 0.f;
    float acc = 0.f;
    for (int j = 15; j >= 0; j--) {
        acc += Wp[(size_t)j * HF + col];
        g_SB[(size_t)j * HF + col] = acc + bpv;
    }
    acc = 0.f;
    for (int j = 15; j >= 0; j--) {
        acc += Wp[(size_t)(16 + j) * HF + col];
        g_T[(size_t)j * HF + col] = acc;
    }
}

// ------------------- jmin / sign per relative position --------------------
__global__ void k_postab() {
    int p = blockIdx.x * 256 + threadIdx.x;
    if (p >= NPOS) return;
    double a = fabs((double)(p - 511));
    int jm = 16;
    double l = log10(497.0) / 16.0;
    for (int i = 0; i < 16; i++) {
        double w = (double)i + pow(10.0, l * (double)i);
        if (w > a) { jm = i; break; }
    }
    g_jmin[p] = jm;
    g_sign[p] = (p > 511) ? 1.f : (p < 511 ? -1.f : 0.f);
}

// ------------------- G/H tables (tiled: head x rowchunk) ------------------
__global__ void k_gh(const float* __restrict__ qrb, const float* __restrict__ krb) {
    __shared__ float Ss[17][132];
    __shared__ float Ts[17][132];
    __shared__ float qs[32][132];
    int chunk = blockIdx.x, h = blockIdx.y, which = blockIdx.z;
    const float* src  = which ? g_k : g_q;
    const float* bias = which ? krb : qrb;
    float* G  = which ? g_Gk : g_Gq;
    float* Hh = which ? g_Hk : g_Hq;
    int tid = threadIdx.x;                    // 256
    for (int i = tid; i < 17 * FF; i += 256) {
        int j = i >> 7, f = i & 127;
        Ss[j][f] = g_SB[(size_t)j * HF + h * FF + f];
        Ts[j][f] = g_T [(size_t)j * HF + h * FF + f];
    }
    for (int i = tid; i < 32 * FF; i += 256) {
        int r = i >> 7, f = i & 127;
        qs[r][f] = src[(size_t)(chunk * 32 + r) * HF + h * FF + f] + bias[h * FF + f];
    }
    __syncthreads();
    for (int t = tid; t < 544; t += 256) {
        int r = t / 17, j = t % 17;
        const float4* q4 = (const float4*)&qs[r][0];
        const float4* s4 = (const float4*)&Ss[j][0];
        const float4* t4 = (const float4*)&Ts[j][0];
        float ag = 0.f, ah = 0.f;
        #pragma unroll
        for (int f = 0; f < 32; f++) {
            float4 q = q4[f], sv = s4[f], tv = t4[f];
            ag += q.x * sv.x + q.y * sv.y + q.z * sv.z + q.w * sv.w;
            ah += q.x * tv.x + q.y * tv.y + q.z * tv.z + q.w * tv.w;
        }
        size_t o = (size_t)(chunk * 32 + r) * 544 + h * 17 + j;
        G[o] = ag; Hh[o] = ah;
    }
}

// ------------------- pre-contract G/H with Wout, sign-combined ------------
__global__ void k_ghw(const float* __restrict__ Wout) {
    int row = blockIdx.x, j = blockIdx.y, f = threadIdx.x;   // 128 threads
    __shared__ float sgq[32], shq[32], sgk[32], shk[32];
    if (f < 32) {
        sgq[f] = g_Gq[(size_t)row * 544 + f * 17 + j];
        shq[f] = g_Hq[(size_t)row * 544 + f * 17 + j];
        sgk[f] = g_Gk[(size_t)row * 544 + f * 17 + j];
        shk[f] = g_Hk[(size_t)row * 544 + f * 17 + j];
    }
    __syncthreads();
    float ag = 0.f, ah = 0.f, bg = 0.f, bh = 0.f;
    #pragma unroll
    for (int h = 0; h < 32; h++) {
        float w = Wout[h * FF + f];
        ag += sgq[h] * w; ah += shq[h] * w;
        bg += sgk[h] * w; bh += shk[h] * w;
    }
    size_t o = ((size_t)row * 17 + j) * FF + f;
    g_QP[o] = ag + ah; g_QM[o] = ag - ah;
    g_KP[o] = bg + bh; g_KM[o] = bg - bh;
}

// ------------------- final pair assembly (scalar, proven) -----------------
__global__ void k_pair(const float* __restrict__ Wout, const float* __restrict__ bout,
                       float* __restrict__ out) {
    __shared__ float S_s[32 * 256];
    __shared__ int   jm1s[31], jm2s[31];
    __shared__ float sg1s[31];
    int b = blockIdx.z;
    int q0 = blockIdx.y * 16, k0 = blockIdx.x * 16;
    int tid = threadIdx.x;                    // 256
    int f0 = (tid & 63) * 2;
    int g = tid >> 6;
    for (int i = tid; i < 2048; i += 256) {
        int flat = i * 4;
        int h = flat >> 8, qi = (flat >> 4) & 15, k4 = flat & 15;
        *(float4*)&S_s[flat] =
            *(const float4*)&g_S[((size_t)(b * 32 + h) * PP + q0 + qi) * PP + k0 + k4];
    }
    if (tid < 31) {
        int p1 = k0 - q0 + 496 + tid;
        jm1s[tid] = g_jmin[p1]; sg1s[tid] = g_sign[p1];
        jm2s[tid] = g_jmin[1022 - p1];
    }
    float2 wr[32];
    #pragma unroll
    for (int h = 0; h < 32; h++) wr[h] = *(const float2*)&Wout[h * FF + f0];
    float2 bo = *(const float2*)&bout[f0];
    __syncthreads();
    for (int i = 0; i < 64; i++) {
        int p = g * 64 + i;
        int qi = p >> 4, kj = p & 15;
        float a0 = 0.f, a1 = 0.f;
        #pragma unroll
        for (int h = 0; h < 32; h++) {
            float s = S_s[h * 256 + qi * 16 + kj];
            a0 += s * wr[h].x; a1 += s * wr[h].y;
        }
        int t = kj - qi + 15;
        int j1 = jm1s[t], j2 = jm2s[t];
        float s1 = sg1s[t];
        int qrow = b * PP + q0 + qi, krow = b * PP + k0 + kj;
        size_t oq = ((size_t)qrow * 17 + j1) * FF + f0;
        size_t ok = ((size_t)krow * 17 + j2) * FF + f0;
        float2 rq, rk;
        if (s1 > 0.f)      { rq = *(const float2*)&g_QP[oq]; rk = *(const float2*)&g_KM[ok]; }
        else if (s1 < 0.f) { rq = *(const float2*)&g_QM[oq]; rk = *(const float2*)&g_KP[ok]; }
        else {
            float2 p1v = *(const float2*)&g_QP[oq], m1 = *(const float2*)&g_QM[oq];
            float2 p2v = *(const float2*)&g_KP[ok], m2 = *(const float2*)&g_KM[ok];
            rq = make_float2(0.5f * (p1v.x + m1.x), 0.5f * (p1v.y + m1.y));
            rk = make_float2(0.5f * (p2v.x + m2.x), 0.5f * (p2v.y + m2.y));
        }
        float2 yq = *(const float2*)&g_yqk[(size_t)qrow * 256 + f0];
        float2 yk = *(const float2*)&g_yqk[(size_t)krow * 256 + 128 + f0];
        float2 o;
        o.x = a0 + 0.25f * (rq.x + rk.x) + bo.x + yq.x + yk.x;
        o.y = a1 + 0.25f * (rq.y + rk.y) + bo.y + yq.y + yk.y;
        *(float2*)&out[((size_t)qrow * PP + k0 + kj) * FF + f0] = o;
    }
}

// ------------------- launcher ---------------------------------------------
extern "C" void kernel_launch(void* const* d_in, const int* in_sizes, int n_in,
                              void* d_out, int out_size) {
    const float* x    = (const float*)d_in[0];
    const float* ns   = (const float*)d_in[1];
    const float* nms  = (const float*)d_in[2];
    const float* Wq   = (const float*)d_in[3];
    const float* Wk   = (const float*)d_in[4];
    const float* Wp   = (const float*)d_in[5];
    const float* bp   = (const float*)d_in[6];
    const float* qrb  = (const float*)d_in[7];
    const float* krb  = (const float*)d_in[8];
    const float* Wyq  = (const float*)d_in[9];
    const float* Wyk  = (const float*)d_in[10];
    const float* Wout = (const float*)d_in[11];
    const float* bout = (const float*)d_in[12];
    float* out = (float*)d_out;

    cudaFuncSetAttribute(k_mm_mma, cudaFuncAttributeMaxDynamicSharedMemorySize, MM_SMEM);

    k_pool<<<1024, 384>>>(x, ns, nms);                 // 1
    k_tr<<<dim3(128, 48), dim3(32, 8)>>>(Wq, 0);       // 2
    k_tr<<<dim3(128, 48), dim3(32, 8)>>>(Wk, 1);       // 3
    k_mm_mma<<<dim3(32, 8, 2), 256, MM_SMEM>>>(0);     // 4  <- profiled slot
    k_suffix<<<16, 256>>>(Wp, bp);                     // 5
    k_postab<<<4, 256>>>();                            // 6
    k_tr<<<dim3(4, 48), dim3(32, 8)>>>(Wyq, 2);        // 7
    k_tr<<<dim3(4, 48), dim3(32, 8)>>>(Wyk, 3);        // 8
    k_mm_mma<<<dim3(2, 8, 1), 256, MM_SMEM>>>(3);      // 9
    k_gh<<<dim3(32, 32, 2), 256>>>(qrb, krb);          // 10
    k_ghw<<<dim3(1024, 17), 128>>>(Wout);              // 11
    k_mm_mma<<<dim3(4, 4, 64), 256, MM_SMEM>>>(2);     // 12
    k_pair<<<dim3(32, 32, 2), 256>>>(Wout, bout, out); // 13
}

// round 14
// speedup vs baseline: 1.0648x; 1.0648x over previous
#include <cuda_runtime.h>
#include <math.h>
#include <stdint.h>

#define CCH 1536
#define PP 512
#define HH 32
#define FF 128
#define HF 4096
#define NROWS 1024
#define NPOS 1023
#define GK 1536
#define GN 4096

// ------------------- scratch (device globals, no allocation) --------------
__device__ float g_xn[NROWS * CCH];
__device__ float g_xa[NROWS * CCH];
__device__ float g_q [NROWS * HF];
__device__ float g_k [NROWS * HF];
__device__ float g_yqk[NROWS * 256];          // [row][0:128)=yq, [128:256)=yk
__device__ float g_SB[17 * HF];
__device__ float g_T [17 * HF];
__device__ float g_Gq[NROWS * 544];
__device__ float g_Hq[NROWS * 544];
__device__ float g_Gk[NROWS * 544];
__device__ float g_Hk[NROWS * 544];
__device__ float g_QP[NROWS * 17 * FF];       // (Gq+Hq)@Wout
__device__ float g_QM[NROWS * 17 * FF];       // (Gq-Hq)@Wout
__device__ float g_KP[NROWS * 17 * FF];
__device__ float g_KM[NROWS * 17 * FF];
__device__ float g_S[(size_t)64 * PP * PP];   // [b*32+h][q][k]
__device__ float g_WqT[(size_t)GN * GK];      // K-major weights
__device__ float g_WkT[(size_t)GN * GK];
__device__ float g_WyT[(size_t)256 * GK];     // rows 0-127: WyqT, 128-255: WykT
__device__ int   g_jmin[NPOS];
__device__ float g_sign[NPOS];

// ------------------- cp.async / mma / ldmatrix helpers --------------------
__device__ __forceinline__ uint32_t smem_u32(const void* p) {
    uint32_t a;
    asm("{ .reg .u64 t; cvta.to.shared.u64 t, %1; cvt.u32.u64 %0, t; }" : "=r"(a) : "l"(p));
    return a;
}
__device__ __forceinline__ void cp_async16(void* smem_dst, const void* gmem_src) {
    uint32_t d = smem_u32(smem_dst);
    asm volatile("cp.async.ca.shared.global [%0], [%1], 16;" :: "r"(d), "l"(gmem_src));
}
#define CP_COMMIT() asm volatile("cp.async.commit_group;" ::: "memory")
#define CP_WAIT(n)  asm volatile("cp.async.wait_group %0;" :: "n"(n) : "memory")

#define LDSM4(r0, r1, r2, r3, addr) \
    asm volatile("ldmatrix.sync.aligned.m8n8.x4.shared.b16 {%0,%1,%2,%3}, [%4];" \
        : "=r"(r0), "=r"(r1), "=r"(r2), "=r"(r3) : "r"(addr))

__device__ __forceinline__ void mma_tf32(float* c, const float* a, const float* b) {
    asm volatile(
        "mma.sync.aligned.m16n8k8.row.col.f32.tf32.tf32.f32 "
        "{%0,%1,%2,%3}, {%4,%5,%6,%7}, {%8,%9}, {%0,%1,%2,%3};"
        : "+f"(c[0]), "+f"(c[1]), "+f"(c[2]), "+f"(c[3])
        : "r"(__float_as_uint(a[0])), "r"(__float_as_uint(a[1])),
          "r"(__float_as_uint(a[2])), "r"(__float_as_uint(a[3])),
          "r"(__float_as_uint(b[0])), "r"(__float_as_uint(b[1])));
}

__device__ __forceinline__ float tf32_rna(float x) {
    uint32_t u;
    asm("cvt.rna.tf32.f32 %0, %1;" : "=r"(u) : "f"(x));
    return __uint_as_float(u);
}

// 3xTF32 compensated mma: near-fp32 accuracy
__device__ __forceinline__ void mma_tf32x3(float* c, const float* a, const float* b) {
    float ah[4], al[4], bh[2], bl[2];
    #pragma unroll
    for (int i = 0; i < 4; i++) { ah[i] = tf32_rna(a[i]); al[i] = a[i] - ah[i]; }
    #pragma unroll
    for (int i = 0; i < 2; i++) { bh[i] = tf32_rna(b[i]); bl[i] = b[i] - bh[i]; }
    mma_tf32(c, al, bh);
    mma_tf32(c, ah, bl);
    mma_tf32(c, ah, bh);
}

// ------------------- tensor-core GEMM (tf32 mma.sync + ldmatrix) ----------
// mode 0: z=0: g_q = g_xn @ WqT^T ; z=1: g_k = g_xn @ WkT^T  (K=1536) grid (32,8,2)
// mode 2: g_S = Q @ K^T per (b,h) (K=128) grid (4,4,64)
// mode 3: g_yqk = g_xa @ WyT^T   (K=1536)  grid (2,8)  [3xTF32 precise]
#define BK 16
#define SKP 20

__global__ __launch_bounds__(256, 2) void k_mm_mma(int mode) {
    __shared__ float As[2][128][SKP];
    __shared__ float Bs[2][128][SKP];
    int tid = threadIdx.x, lane = tid & 31, wid = tid >> 5;
    int n0 = blockIdx.x * 128, m0 = blockIdx.y * 128;

    const float *A, *B; float* C;
    int lda, ldb, ldc, Kd;
    if (mode == 2) {
        int z = blockIdx.z, b = z >> 5, h = z & 31;
        A = g_q + ((size_t)(b * PP + m0)) * HF + h * FF;
        B = g_k + ((size_t)(b * PP + n0)) * HF + h * FF;
        C = g_S + ((size_t)z * PP + m0) * PP + n0;
        lda = HF; ldb = HF; ldc = PP; Kd = FF;
    } else if (mode == 3) {
        A = g_xa + (size_t)m0 * GK;
        B = g_WyT + (size_t)n0 * GK;
        C = g_yqk + (size_t)m0 * 256 + n0;
        lda = GK; ldb = GK; ldc = 256; Kd = GK;
    } else {
        int which = blockIdx.z;
        A = g_xn + (size_t)m0 * GK;
        B = (which ? g_WkT : g_WqT) + (size_t)n0 * GK;
        C = (which ? g_k : g_q) + (size_t)m0 * GN + n0;
        lda = GK; ldb = GK; ldc = GN; Kd = GK;
    }

    int lr = tid >> 2, lc = (tid & 3) * 4;
    int NS = Kd / BK;

    #pragma unroll
    for (int u = 0; u < 2; u++) {
        int r = lr + u * 64;
        cp_async16(&As[0][r][lc], A + (size_t)r * lda + lc);
        cp_async16(&Bs[0][r][lc], B + (size_t)r * ldb + lc);
    }
    CP_COMMIT();

    int wm = (wid & 1) * 64;
    int wn = (wid >> 1) * 32;
    float acc[4][4][4];
    #pragma unroll
    for (int i = 0; i < 4; i++)
        #pragma unroll
        for (int j = 0; j < 4; j++)
            #pragma unroll
            for (int r = 0; r < 4; r++) acc[i][j][r] = 0.f;

    // ldmatrix per-lane byte offsets within a stage
    // A x4: row = lane&15 within 16-row tile, col = (lane>>4)*4
    uint32_t aOff = (uint32_t)(((lane & 15) * SKP + (lane >> 4) * 4) * 4);
    // B x4 (two nt packed): row = (lane>>4)*8 + (lane&7), col = ((lane>>3)&1)*4
    uint32_t bOff = (uint32_t)((((lane >> 4) * 8 + (lane & 7)) * SKP + ((lane >> 3) & 1) * 4) * 4);
    uint32_t baseA = smem_u32(&As[0][0][0]);
    uint32_t baseB = smem_u32(&Bs[0][0][0]);
    const uint32_t stageB = 128 * SKP * 4;

    int s = 0;
    for (int kt = 0; kt < NS; kt++) {
        if (kt + 1 < NS) {
            int k0 = (kt + 1) * BK;
            #pragma unroll
            for (int u = 0; u < 2; u++) {
                int r = lr + u * 64;
                cp_async16(&As[s ^ 1][r][lc], A + (size_t)r * lda + k0 + lc);
                cp_async16(&Bs[s ^ 1][r][lc], B + (size_t)r * ldb + k0 + lc);
            }
            CP_COMMIT();
            CP_WAIT(1);
        } else {
            CP_WAIT(0);
        }
        __syncthreads();
        uint32_t sA = baseA + s * stageB + (uint32_t)(wm * SKP * 4) + aOff;
        uint32_t sB = baseB + s * stageB + (uint32_t)(wn * SKP * 4) + bOff;
        #pragma unroll
        for (int kk = 0; kk < 16; kk += 8) {
            uint32_t a[4][4], b[2][4];
            #pragma unroll
            for (int mt = 0; mt < 4; mt++)
                LDSM4(a[mt][0], a[mt][1], a[mt][2], a[mt][3],
                      sA + (uint32_t)(mt * 16 * SKP * 4 + kk * 4));
            #pragma unroll
            for (int p = 0; p < 2; p++)
                LDSM4(b[p][0], b[p][1], b[p][2], b[p][3],
                      sB + (uint32_t)(p * 16 * SKP * 4 + kk * 4));
            if (mode == 3) {
                #pragma unroll
                for (int mt = 0; mt < 4; mt++)
                    #pragma unroll
                    for (int p = 0; p < 2; p++) {
                        mma_tf32x3(acc[mt][p * 2    ], (const float*)a[mt], (const float*)&b[p][0]);
                        mma_tf32x3(acc[mt][p * 2 + 1], (const float*)a[mt], (const float*)&b[p][2]);
                    }
            } else {
                #pragma unroll
                for (int mt = 0; mt < 4; mt++)
                    #pragma unroll
                    for (int p = 0; p < 2; p++) {
                        mma_tf32(acc[mt][p * 2    ], (const float*)a[mt], (const float*)&b[p][0]);
                        mma_tf32(acc[mt][p * 2 + 1], (const float*)a[mt], (const float*)&b[p][2]);
                    }
            }
        }
        __syncthreads();
        s ^= 1;
    }

    int g4 = lane >> 2, r4 = lane & 3;
    #pragma unroll
    for (int mt = 0; mt < 4; mt++) {
        #pragma unroll
        for (int nt = 0; nt < 4; nt++) {
            int m = wm + mt * 16 + g4;
            int n = wn + nt * 8 + r4 * 2;
            *(float2*)&C[(size_t)m * ldc + n] =
                make_float2(acc[mt][nt][0], acc[mt][nt][1]);
            *(float2*)&C[(size_t)(m + 8) * ldc + n] =
                make_float2(acc[mt][nt][2], acc[mt][nt][3]);
        }
    }
}

// ------------------- transposes to K-major --------------------------------
__global__ void k_tr(const float* __restrict__ W, int which) {
    __shared__ float t[32][33];
    int Cc = (which < 2) ? GN : FF;
    float* dst; int roff = 0;
    if (which == 0) dst = g_WqT;
    else if (which == 1) dst = g_WkT;
    else { dst = g_WyT; roff = (which - 2) * FF; }
    int n0 = blockIdx.x * 32, k0 = blockIdx.y * 32;
    int tx = threadIdx.x, ty = threadIdx.y;      // (32, 8)
    #pragma unroll
    for (int i = 0; i < 32; i += 8)
        t[ty + i][tx] = W[(size_t)(k0 + ty + i) * Cc + n0 + tx];
    __syncthreads();
    #pragma unroll
    for (int i = 0; i < 32; i += 8)
        dst[(size_t)(roff + n0 + ty + i) * GK + k0 + tx] = t[tx][ty + i];
}

// ------------------- avgpool + RMS scale + gelu (float4) ------------------
__global__ void k_pool(const float* __restrict__ x, const float* __restrict__ ns,
                       const float* __restrict__ nms) {
    int bp = blockIdx.x;
    size_t base = (size_t)bp * 16 * CCH;
    int c4 = threadIdx.x * 4;                 // 384 threads cover 1536
    float4 s = make_float4(0.f, 0.f, 0.f, 0.f);
    #pragma unroll
    for (int w = 0; w < 16; w++) {
        float4 v = *(const float4*)&x[base + (size_t)w * CCH + c4];
        s.x += v.x; s.y += v.y; s.z += v.z; s.w += v.w;
    }
    float4 nsv = *(const float4*)&ns[c4];
    float4 nmv = *(const float4*)&nms[c4];
    float4 vn, va;
    vn.x = s.x * 0.0625f * (nsv.x * rsqrtf(nmv.x + 1e-5f));
    vn.y = s.y * 0.0625f * (nsv.y * rsqrtf(nmv.y + 1e-5f));
    vn.z = s.z * 0.0625f * (nsv.z * rsqrtf(nmv.z + 1e-5f));
    vn.w = s.w * 0.0625f * (nsv.w * rsqrtf(nmv.w + 1e-5f));
    va.x = 0.5f * vn.x * (1.f + erff(vn.x * 0.70710678118654752f));
    va.y = 0.5f * vn.y * (1.f + erff(vn.y * 0.70710678118654752f));
    va.z = 0.5f * vn.z * (1.f + erff(vn.z * 0.70710678118654752f));
    va.w = 0.5f * vn.w * (1.f + erff(vn.w * 0.70710678118654752f));
    *(float4*)&g_xn[(size_t)bp * CCH + c4] = vn;
    *(float4*)&g_xa[(size_t)bp * CCH + c4] = va;
}

// ------------------- suffix sums of Wp (+ bp) -----------------------------
__global__ void k_suffix(const float* __restrict__ Wp, const float* __restrict__ bp) {
    int col = blockIdx.x * 256 + threadIdx.x;
    if (col >= HF) return;
    float bpv = bp[col];
    g_SB[16 * HF + col] = bpv;
    g_T [16 * HF + col] = 0.f;
    float acc = 0.f;
    for (int j = 15; j >= 0; j--) {
        acc += Wp[(size_t)j * HF + col];
        g_SB[(size_t)j * HF + col] = acc + bpv;
    }
    acc = 0.f;
    for (int j = 15; j >= 0; j--) {
        acc += Wp[(size_t)(16 + j) * HF + col];
        g_T[(size_t)j * HF + col] = acc;
    }
}

// ------------------- jmin / sign per relative position --------------------
__global__ void k_postab() {
    int p = blockIdx.x * 256 + threadIdx.x;
    if (p >= NPOS) return;
    double a = fabs((double)(p - 511));
    int jm = 16;
    double l = log10(497.0) / 16.0;
    for (int i = 0; i < 16; i++) {
        double w = (double)i + pow(10.0, l * (double)i);
        if (w > a) { jm = i; break; }
    }
    g_jmin[p] = jm;
    g_sign[p] = (p > 511) ? 1.f : (p < 511 ? -1.f : 0.f);
}

// ------------------- G/H tables (tiled: head x rowchunk) ------------------
__global__ void k_gh(const float* __restrict__ qrb, const float* __restrict__ krb) {
    __shared__ float Ss[17][132];
    __shared__ float Ts[17][132];
    __shared__ float qs[32][132];
    int chunk = blockIdx.x, h = blockIdx.y, which = blockIdx.z;
    const float* src  = which ? g_k : g_q;
    const float* bias = which ? krb : qrb;
    float* G  = which ? g_Gk : g_Gq;
    float* Hh = which ? g_Hk : g_Hq;
    int tid = threadIdx.x;                    // 256
    for (int i = tid; i < 17 * FF; i += 256) {
        int j = i >> 7, f = i & 127;
        Ss[j][f] = g_SB[(size_t)j * HF + h * FF + f];
        Ts[j][f] = g_T [(size_t)j * HF + h * FF + f];
    }
    for (int i = tid; i < 32 * FF; i += 256) {
        int r = i >> 7, f = i & 127;
        qs[r][f] = src[(size_t)(chunk * 32 + r) * HF + h * FF + f] + bias[h * FF + f];
    }
    __syncthreads();
    for (int t = tid; t < 544; t += 256) {
        int r = t / 17, j = t % 17;
        const float4* q4 = (const float4*)&qs[r][0];
        const float4* s4 = (const float4*)&Ss[j][0];
        const float4* t4 = (const float4*)&Ts[j][0];
        float ag = 0.f, ah = 0.f;
        #pragma unroll
        for (int f = 0; f < 32; f++) {
            float4 q = q4[f], sv = s4[f], tv = t4[f];
            ag += q.x * sv.x + q.y * sv.y + q.z * sv.z + q.w * sv.w;
            ah += q.x * tv.x + q.y * tv.y + q.z * tv.z + q.w * tv.w;
        }
        size_t o = (size_t)(chunk * 32 + r) * 544 + h * 17 + j;
        G[o] = ag; Hh[o] = ah;
    }
}

// ------------------- pre-contract G/H with Wout, sign-combined ------------
__global__ void k_ghw(const float* __restrict__ Wout) {
    int row = blockIdx.x, j = blockIdx.y, f = threadIdx.x;   // 128 threads
    __shared__ float sgq[32], shq[32], sgk[32], shk[32];
    if (f < 32) {
        sgq[f] = g_Gq[(size_t)row * 544 + f * 17 + j];
        shq[f] = g_Hq[(size_t)row * 544 + f * 17 + j];
        sgk[f] = g_Gk[(size_t)row * 544 + f * 17 + j];
        shk[f] = g_Hk[(size_t)row * 544 + f * 17 + j];
    }
    __syncthreads();
    float ag = 0.f, ah = 0.f, bg = 0.f, bh = 0.f;
    #pragma unroll
    for (int h = 0; h < 32; h++) {
        float w = Wout[h * FF + f];
        ag += sgq[h] * w; ah += shq[h] * w;
        bg += sgk[h] * w; bh += shk[h] * w;
    }
    size_t o = ((size_t)row * 17 + j) * FF + f;
    g_QP[o] = ag + ah; g_QM[o] = ag - ah;
    g_KP[o] = bg + bh; g_KM[o] = bg - bh;
}

// ------------------- final pair assembly (scalar, proven) -----------------
__global__ void k_pair(const float* __restrict__ Wout, const float* __restrict__ bout,
                       float* __restrict__ out) {
    __shared__ float S_s[32 * 256];
    __shared__ int   jm1s[31], jm2s[31];
    __shared__ float sg1s[31];
    int b = blockIdx.z;
    int q0 = blockIdx.y * 16, k0 = blockIdx.x * 16;
    int tid = threadIdx.x;                    // 256
    int f0 = (tid & 63) * 2;
    int g = tid >> 6;
    for (int i = tid; i < 2048; i += 256) {
        int flat = i * 4;
        int h = flat >> 8, qi = (flat >> 4) & 15, k4 = flat & 15;
        *(float4*)&S_s[flat] =
            *(const float4*)&g_S[((size_t)(b * 32 + h) * PP + q0 + qi) * PP + k0 + k4];
    }
    if (tid < 31) {
        int p1 = k0 - q0 + 496 + tid;
        jm1s[tid] = g_jmin[p1]; sg1s[tid] = g_sign[p1];
        jm2s[tid] = g_jmin[1022 - p1];
    }
    float2 wr[32];
    #pragma unroll
    for (int h = 0; h < 32; h++) wr[h] = *(const float2*)&Wout[h * FF + f0];
    float2 bo = *(const float2*)&bout[f0];
    __syncthreads();
    for (int i = 0; i < 64; i++) {
        int p = g * 64 + i;
        int qi = p >> 4, kj = p & 15;
        float a0 = 0.f, a1 = 0.f;
        #pragma unroll
        for (int h = 0; h < 32; h++) {
            float s = S_s[h * 256 + qi * 16 + kj];
            a0 += s * wr[h].x; a1 += s * wr[h].y;
        }
        int t = kj - qi + 15;
        int j1 = jm1s[t], j2 = jm2s[t];
        float s1 = sg1s[t];
        int qrow = b * PP + q0 + qi, krow = b * PP + k0 + kj;
        size_t oq = ((size_t)qrow * 17 + j1) * FF + f0;
        size_t ok = ((size_t)krow * 17 + j2) * FF + f0;
        float2 rq, rk;
        if (s1 > 0.f)      { rq = *(const float2*)&g_QP[oq]; rk = *(const float2*)&g_KM[ok]; }
        else if (s1 < 0.f) { rq = *(const float2*)&g_QM[oq]; rk = *(const float2*)&g_KP[ok]; }
        else {
            float2 p1v = *(const float2*)&g_QP[oq], m1 = *(const float2*)&g_QM[oq];
            float2 p2v = *(const float2*)&g_KP[ok], m2 = *(const float2*)&g_KM[ok];
            rq = make_float2(0.5f * (p1v.x + m1.x), 0.5f * (p1v.y + m1.y));
            rk = make_float2(0.5f * (p2v.x + m2.x), 0.5f * (p2v.y + m2.y));
        }
        float2 yq = *(const float2*)&g_yqk[(size_t)qrow * 256 + f0];
        float2 yk = *(const float2*)&g_yqk[(size_t)krow * 256 + 128 + f0];
        float2 o;
        o.x = a0 + 0.25f * (rq.x + rk.x) + bo.x + yq.x + yk.x;
        o.y = a1 + 0.25f * (rq.y + rk.y) + bo.y + yq.y + yk.y;
        *(float2*)&out[((size_t)qrow * PP + k0 + kj) * FF + f0] = o;
    }
}

// ------------------- launcher ---------------------------------------------
extern "C" void kernel_launch(void* const* d_in, const int* in_sizes, int n_in,
                              void* d_out, int out_size) {
    const float* x    = (const float*)d_in[0];
    const float* ns   = (const float*)d_in[1];
    const float* nms  = (const float*)d_in[2];
    const float* Wq   = (const float*)d_in[3];
    const float* Wk   = (const float*)d_in[4];
    const float* Wp   = (const float*)d_in[5];
    const float* bp   = (const float*)d_in[6];
    const float* qrb  = (const float*)d_in[7];
    const float* krb  = (const float*)d_in[8];
    const float* Wyq  = (const float*)d_in[9];
    const float* Wyk  = (const float*)d_in[10];
    const float* Wout = (const float*)d_in[11];
    const float* bout = (const float*)d_in[12];
    float* out = (float*)d_out;

    k_pool<<<1024, 384>>>(x, ns, nms);                 // 1
    k_tr<<<dim3(128, 48), dim3(32, 8)>>>(Wq, 0);       // 2
    k_tr<<<dim3(128, 48), dim3(32, 8)>>>(Wk, 1);       // 3
    k_mm_mma<<<dim3(32, 8, 2), 256>>>(0);              // 4  <- profiled slot
    k_suffix<<<16, 256>>>(Wp, bp);                     // 5
    k_postab<<<4, 256>>>();                            // 6
    k_tr<<<dim3(4, 48), dim3(32, 8)>>>(Wyq, 2);        // 7
    k_tr<<<dim3(4, 48), dim3(32, 8)>>>(Wyk, 3);        // 8
    k_mm_mma<<<dim3(2, 8, 1), 256>>>(3);               // 9
    k_gh<<<dim3(32, 32, 2), 256>>>(qrb, krb);          // 10
    k_ghw<<<dim3(1024, 17), 128>>>(Wout);              // 11
    k_mm_mma<<<dim3(4, 4, 64), 256>>>(2);              // 12
    k_pair<<<dim3(32, 32, 2), 256>>>(Wout, bout, out); // 13
}